// round 3
// baseline (speedup 1.0000x reference)
#include <cuda_runtime.h>
#include <cuda_bf16.h>
#include <cstdint>
#include <cstddef>

// Problem constants (fixed by the dataset)
#define BATCH 16
#define NLOG  512
#define Q     2048      // N_PHYS
#define EDG   2048
#define MROWS (BATCH * NLOG)   // 8192

// GEMM tiling
#define BM 128
#define BN 128
#define BK 32
#define LDA 40    // BK + 8 pad (bf16 elems)
#define LDB 136   // BN + 8 pad

// ---------------- scratch (device globals; no allocation allowed) ----------
__device__ __nv_bfloat16 g_Pb[(size_t)MROWS * Q];   // P in bf16     (32 MB)
__device__ __nv_bfloat16 g_Bn[(size_t)Q * Q];       // A_hw bf16 [k][n] (8 MB)
__device__ __nv_bfloat16 g_PA[(size_t)MROWS * Q];   // P @ A  bf16   (32 MB)
__device__ float g_edot[BATCH * EDG];               // per-edge w*score
__device__ float g_num[BATCH];
__device__ float g_den[BATCH];

// ---------------- small PTX helpers ----------------------------------------
__device__ __forceinline__ void cp16(void* s, const void* g) {
    uint32_t sa = (uint32_t)__cvta_generic_to_shared(s);
    asm volatile("cp.async.cg.shared.global [%0], [%1], 16;\n" :: "r"(sa), "l"(g));
}
__device__ __forceinline__ void cp_commit() {
    asm volatile("cp.async.commit_group;\n" ::);
}
__device__ __forceinline__ void cp_wait1() {
    asm volatile("cp.async.wait_group 1;\n" ::);
}
__device__ __forceinline__ void cp_wait0() {
    asm volatile("cp.async.wait_group 0;\n" ::);
}
__device__ __forceinline__ void ldsm4(uint32_t& r0, uint32_t& r1, uint32_t& r2, uint32_t& r3,
                                      const void* p) {
    uint32_t a = (uint32_t)__cvta_generic_to_shared(p);
    asm volatile("ldmatrix.sync.aligned.m8n8.x4.shared.b16 {%0,%1,%2,%3}, [%4];"
                 : "=r"(r0), "=r"(r1), "=r"(r2), "=r"(r3) : "r"(a));
}
__device__ __forceinline__ void ldsm4t(uint32_t& r0, uint32_t& r1, uint32_t& r2, uint32_t& r3,
                                       const void* p) {
    uint32_t a = (uint32_t)__cvta_generic_to_shared(p);
    asm volatile("ldmatrix.sync.aligned.m8n8.x4.trans.shared.b16 {%0,%1,%2,%3}, [%4];"
                 : "=r"(r0), "=r"(r1), "=r"(r2), "=r"(r3) : "r"(a));
}
__device__ __forceinline__ void mma16816(float* c, const uint32_t* a, uint32_t b0, uint32_t b1) {
    asm volatile(
        "mma.sync.aligned.m16n8k16.row.col.f32.bf16.bf16.f32 "
        "{%0,%1,%2,%3}, {%4,%5,%6,%7}, {%8,%9}, {%0,%1,%2,%3};"
        : "+f"(c[0]), "+f"(c[1]), "+f"(c[2]), "+f"(c[3])
        : "r"(a[0]), "r"(a[1]), "r"(a[2]), "r"(a[3]), "r"(b0), "r"(b1));
}

// ---------------- kernel 1: P fp32 -> bf16 ----------------------------------
__global__ void conv_p_kernel(const float* __restrict__ P) {
    int i = blockIdx.x * blockDim.x + threadIdx.x;     // each handles 4 floats
    float4 v = reinterpret_cast<const float4*>(P)[i];
    __nv_bfloat162* o = reinterpret_cast<__nv_bfloat162*>(g_Pb);
    o[2 * i + 0] = __floats2bfloat162_rn(v.x, v.y);
    o[2 * i + 1] = __floats2bfloat162_rn(v.z, v.w);
}

// ---------------- kernel 2: A_hw = (d_hw == 1), bf16, [k][n] (no transpose) -
__global__ void build_a_kernel(const int* __restrict__ dhw) {
    int i = blockIdx.x * blockDim.x + threadIdx.x;     // each handles 4 ints
    int4 d = reinterpret_cast<const int4*>(dhw)[i];
    __nv_bfloat162* o = reinterpret_cast<__nv_bfloat162*>(g_Bn);
    o[2 * i + 0] = __floats2bfloat162_rn(d.x == 1 ? 1.f : 0.f, d.y == 1 ? 1.f : 0.f);
    o[2 * i + 1] = __floats2bfloat162_rn(d.z == 1 ? 1.f : 0.f, d.w == 1 ? 1.f : 0.f);
}

// ---------------- kernel 3: PA = Pb @ A (bf16 in, fp32 acc, bf16 out) -------
__device__ __forceinline__ void load_tiles(__nv_bfloat16* As, __nv_bfloat16* Bs,
                                           int m0, int n0, int k0, int tid) {
    // A tile: 128 x 32 bf16 = 512 x 16B
#pragma unroll
    for (int i = 0; i < 2; i++) {
        int c = tid + i * 256;
        int r = c >> 2, cc = (c & 3) << 3;
        cp16(As + r * LDA + cc, g_Pb + (size_t)(m0 + r) * Q + k0 + cc);
    }
    // B tile: 32 x 128 bf16 = 512 x 16B
#pragma unroll
    for (int i = 0; i < 2; i++) {
        int c = tid + i * 256;
        int r = c >> 4, cc = (c & 15) << 3;
        cp16(Bs + r * LDB + cc, g_Bn + (size_t)(k0 + r) * Q + n0 + cc);
    }
}

__global__ __launch_bounds__(256) void gemm_kernel() {
    __shared__ __nv_bfloat16 As[2][BM * LDA];
    __shared__ __nv_bfloat16 Bs[2][BK * LDB];

    const int m0 = blockIdx.y * BM;
    const int n0 = blockIdx.x * BN;
    const int tid = threadIdx.x;
    const int lane = tid & 31;
    const int warp = tid >> 5;
    const int wm = warp & 3;   // 4 warps along M  -> warptile 32
    const int wn = warp >> 2;  // 2 warps along N  -> warptile 64

    float acc[2][8][4];
#pragma unroll
    for (int mt = 0; mt < 2; mt++)
#pragma unroll
        for (int nt = 0; nt < 8; nt++)
#pragma unroll
            for (int j = 0; j < 4; j++) acc[mt][nt][j] = 0.f;

    const int NKT = Q / BK;  // 64
    load_tiles(As[0], Bs[0], m0, n0, 0, tid);
    cp_commit();

    for (int kt = 0; kt < NKT; kt++) {
        const int buf = kt & 1;
        if (kt + 1 < NKT) {
            load_tiles(As[buf ^ 1], Bs[buf ^ 1], m0, n0, (kt + 1) * BK, tid);
            cp_commit();
            cp_wait1();
        } else {
            cp_wait0();
        }
        __syncthreads();

#pragma unroll
        for (int ks = 0; ks < 2; ks++) {           // two k16 steps per BK=32
            uint32_t a[2][4];
#pragma unroll
            for (int mt = 0; mt < 2; mt++) {
                const __nv_bfloat16* p = &As[buf][(wm * 32 + mt * 16 + (lane & 15)) * LDA +
                                                  ks * 16 + (lane >> 4) * 8];
                ldsm4(a[mt][0], a[mt][1], a[mt][2], a[mt][3], p);
            }
            uint32_t b[4][4];
#pragma unroll
            for (int nt4 = 0; nt4 < 4; nt4++) {
                const __nv_bfloat16* p = &Bs[buf][(ks * 16 + (lane & 15)) * LDB +
                                                  wn * 64 + nt4 * 16 + (lane >> 4) * 8];
                ldsm4t(b[nt4][0], b[nt4][1], b[nt4][2], b[nt4][3], p);
            }
#pragma unroll
            for (int mt = 0; mt < 2; mt++)
#pragma unroll
                for (int nt = 0; nt < 8; nt++)
                    mma16816(acc[mt][nt], a[mt],
                             b[nt >> 1][(nt & 1) * 2 + 0],
                             b[nt >> 1][(nt & 1) * 2 + 1]);
        }
        __syncthreads();
    }

    // epilogue: fp32 acc -> bf16 PA
#pragma unroll
    for (int mt = 0; mt < 2; mt++) {
#pragma unroll
        for (int nt = 0; nt < 8; nt++) {
            int row = m0 + wm * 32 + mt * 16 + (lane >> 2);
            int col = n0 + wn * 64 + nt * 8 + (lane & 3) * 2;
            *reinterpret_cast<__nv_bfloat162*>(&g_PA[(size_t)row * Q + col]) =
                __floats2bfloat162_rn(acc[mt][nt][0], acc[mt][nt][1]);
            *reinterpret_cast<__nv_bfloat162*>(&g_PA[(size_t)(row + 8) * Q + col]) =
                __floats2bfloat162_rn(acc[mt][nt][2], acc[mt][nt][3]);
        }
    }
}

// ---------------- kernel 4: per-edge gathered dot, one warp per edge --------
__global__ __launch_bounds__(256) void stage2_kernel(const float* __restrict__ P,
                                                     const int* __restrict__ esrc,
                                                     const int* __restrict__ edst,
                                                     const float* __restrict__ ew) {
    const int warp = threadIdx.x >> 5;
    const int lane = threadIdx.x & 31;
    const int eg = blockIdx.x * 8 + warp;     // 0 .. B*E-1
    const int b = eg >> 11;                   // / EDG
    const int e = eg & (EDG - 1);

    const int src = esrc[b * EDG + e];
    const int dst = edst[b * EDG + e];
    const __nv_bfloat16* pa = &g_PA[(size_t)(b * NLOG + src) * Q];
    const float* pj = &P[(size_t)(b * NLOG + dst) * Q];

    float acc = 0.f;
    for (int q = lane * 8; q < Q; q += 256) {
        uint4 u = *reinterpret_cast<const uint4*>(&pa[q]);
        float4 f0 = *reinterpret_cast<const float4*>(&pj[q]);
        float4 f1 = *reinterpret_cast<const float4*>(&pj[q + 4]);
        const __nv_bfloat162* h = reinterpret_cast<const __nv_bfloat162*>(&u);
        acc += __bfloat162float(h[0].x) * f0.x + __bfloat162float(h[0].y) * f0.y;
        acc += __bfloat162float(h[1].x) * f0.z + __bfloat162float(h[1].y) * f0.w;
        acc += __bfloat162float(h[2].x) * f1.x + __bfloat162float(h[2].y) * f1.y;
        acc += __bfloat162float(h[3].x) * f1.z + __bfloat162float(h[3].y) * f1.w;
    }
#pragma unroll
    for (int o = 16; o; o >>= 1) acc += __shfl_xor_sync(0xffffffffu, acc, o);
    if (lane == 0) g_edot[eg] = acc * ew[b * EDG + e];
}

// ---------------- kernel 5: deterministic per-batch reduction ---------------
__global__ void reduce_batch_kernel(const float* __restrict__ ew) {
    __shared__ float sn[256], sd[256];
    const int b = blockIdx.x;
    const int t = threadIdx.x;
    float n = 0.f, d = 0.f;
    for (int e = t; e < EDG; e += 256) {
        n += g_edot[b * EDG + e];
        d += ew[b * EDG + e];
    }
    sn[t] = n; sd[t] = d;
    __syncthreads();
    for (int s = 128; s > 0; s >>= 1) {
        if (t < s) { sn[t] += sn[t + s]; sd[t] += sd[t + s]; }
        __syncthreads();
    }
    if (t == 0) { g_num[b] = sn[0]; g_den[b] = sd[0]; }
}

// ---------------- kernel 6: final loss --------------------------------------
__global__ void final_kernel(float* __restrict__ out) {
    const int t = threadIdx.x;
    float v = (t < BATCH) ? g_num[t] / fmaxf(g_den[t], 1e-8f) : 0.f;
#pragma unroll
    for (int o = 16; o; o >>= 1) v += __shfl_xor_sync(0xffffffffu, v, o);
    if (t == 0) out[0] = -v / (float)BATCH;
}

// ---------------- launch -----------------------------------------------------
extern "C" void kernel_launch(void* const* d_in, const int* in_sizes, int n_in,
                              void* d_out, int out_size) {
    const float* P   = (const float*)d_in[0];  // [16, 512, 2048]
    const int* dhw   = (const int*)  d_in[1];  // [2048, 2048]
    const int* esrc  = (const int*)  d_in[2];  // [16, 2048]
    const int* edst  = (const int*)  d_in[3];  // [16, 2048]
    const float* ew  = (const float*)d_in[4];  // [16, 2048]
    float* out = (float*)d_out;

    conv_p_kernel<<<(MROWS * Q / 4) / 256, 256>>>(P);        // 16384 blocks
    build_a_kernel<<<(Q * Q / 4) / 256, 256>>>(dhw);         // 4096 blocks
    gemm_kernel<<<dim3(Q / BN, MROWS / BM), 256>>>();        // 16 x 64 blocks
    stage2_kernel<<<(BATCH * EDG) / 8, 256>>>(P, esrc, edst, ew);
    reduce_batch_kernel<<<BATCH, 256>>>(ew);
    final_kernel<<<1, 32>>>(out);
}